// round 12
// baseline (speedup 1.0000x reference)
#include <cuda_runtime.h>
#include <stdint.h>

#define HW    96
#define NPIX  9216          // 96*96
#define NIMG  32
#define NTRAIN 100
#define NPC   50
#define NPAD  52            // per-class padded train count (26 pairs)
#define NPAIR 26
#define CAP   1024
#define PADV  1.0e18f
#define ZSPL  2             // hash-phase block split per (image, class)

struct Keys { unsigned int k[NIMG][4]; };   // per image: kfg0,kfg1,kbg0,kbg1

// ---------------------------------------------------------------------------
// packed f32x2 helpers (sm_103a: two fp32 lanes per FMA-pipe op, rn rounding)
// ---------------------------------------------------------------------------
__device__ __forceinline__ unsigned long long pk2(float lo, float hi)
{
    unsigned long long o;
    asm("mov.b64 %0, {%1, %2};" : "=l"(o) : "f"(lo), "f"(hi));
    return o;
}
__device__ __forceinline__ void upk2(float &lo, float &hi, unsigned long long v)
{
    asm("mov.b64 {%0, %1}, %2;" : "=f"(lo), "=f"(hi) : "l"(v));
}
__device__ __forceinline__ unsigned long long add2(unsigned long long a, unsigned long long b)
{
    unsigned long long o;
    asm("add.rn.f32x2 %0, %1, %2;" : "=l"(o) : "l"(a), "l"(b));
    return o;
}
__device__ __forceinline__ unsigned long long mul2(unsigned long long a, unsigned long long b)
{
    unsigned long long o;
    asm("mul.rn.f32x2 %0, %1, %2;" : "=l"(o) : "l"(a), "l"(b));
    return o;
}
__device__ __forceinline__ unsigned long long fma2(unsigned long long a, unsigned long long b,
                                                   unsigned long long c)
{
    unsigned long long o;
    asm("fma.rn.f32x2 %0, %1, %2, %3;" : "=l"(o) : "l"(a), "l"(b), "l"(c));
    return o;
}

// ---------------------------------------------------------------------------
// threefry2x32 (JAX-exact)
// ---------------------------------------------------------------------------
__host__ __device__ __forceinline__ void threefry2x32(
    unsigned int k0, unsigned int k1,
    unsigned int x0, unsigned int x1,
    unsigned int &o0, unsigned int &o1)
{
    unsigned int ks[3];
    ks[0] = k0; ks[1] = k1; ks[2] = k0 ^ k1 ^ 0x1BD11BDAu;
    x0 += ks[0]; x1 += ks[1];
    const int rot[8] = {13, 15, 26, 6, 17, 29, 16, 24};
#pragma unroll
    for (int i = 0; i < 5; ++i) {
#pragma unroll
        for (int j = 0; j < 4; ++j) {
            int r = rot[(i & 1) * 4 + j];
            x0 += x1;
            x1 = (x1 << r) | (x1 >> (32 - r));
            x1 ^= x0;
        }
        x0 += ks[(i + 1) % 3];
        x1 += ks[(i + 2) % 3] + (unsigned int)(i + 1);
    }
    o0 = x0; o1 = x1;
}

// partitionable-mode 32-bit random word for flat index i (iota64: hi=0, lo=i)
__device__ __forceinline__ unsigned int tf_bits32(unsigned int k0, unsigned int k1,
                                                  unsigned int i)
{
    unsigned int r0, r1;
    threefry2x32(k0, k1, 0u, i, r0, r1);
    return r0 ^ r1;
}

__device__ __forceinline__ float bits_to_unit_float(unsigned int bits)
{
    unsigned int fb = (bits >> 9) | 0x3f800000u;
    return __uint_as_float(fb) - 1.0f;
}

__device__ __forceinline__ float clip01(float x)
{
    return fminf(fmaxf(x, 0.0f), 1.0f);
}

// ---------------------------------------------------------------------------
// scratch (no cudaMalloc allowed) — all slots fully overwritten every run
// ---------------------------------------------------------------------------
__device__ float              g_score[NIMG][2][NPIX];       // 2.36 MB
__device__ int                g_hist[NIMG][2][ZSPL][256];   // per-z partial hists
__device__ int                g_sel[NIMG][2][NPC];
__device__ unsigned long long g_tr2[NIMG][2][5][NPAIR];     // NEGATED std. train pairs
__device__ float              g_mean[NIMG][5];
__device__ float              g_std[NIMG][5];

// ---------------------------------------------------------------------------
// Kernel 0: scores + partial histograms.  grid (NIMG, 2, ZSPL), 1024 thr.
// 128 blocks -> one wave across the chip for the threefry-heavy phase.
// ---------------------------------------------------------------------------
__global__ __launch_bounds__(1024) void k0_score(const float* __restrict__ img, Keys kp)
{
    const int b = blockIdx.x;
    const int pass = blockIdx.y;              // 0 = fg, 1 = bg
    const int z = blockIdx.z;
    const int t = threadIdx.x;
    const float* im = img + (size_t)b * NPIX * 3;
    const float4* im4 = (const float4*)im;    // 4 px = 3 float4

    __shared__ int hist[256];
    __shared__ int chmaxi[3];

    if (t < 3) chmaxi[t] = 0;
    if (t < 256) hist[t] = 0;
    __syncthreads();

    // ---- channel max over FULL image (both z blocks need the same cm) ----
    float m0 = 0.f, m1 = 0.f, m2 = 0.f;
    for (int g = t; g < NPIX / 4; g += 1024) {
        float4 A = im4[g * 3 + 0];
        float4 Bv = im4[g * 3 + 1];
        float4 C = im4[g * 3 + 2];
        m0 = fmaxf(m0, fmaxf(fmaxf(clip01(A.x / 255.0f), clip01(A.w / 255.0f)),
                             fmaxf(clip01(Bv.z / 255.0f), clip01(C.y / 255.0f))));
        m1 = fmaxf(m1, fmaxf(fmaxf(clip01(A.y / 255.0f), clip01(Bv.x / 255.0f)),
                             fmaxf(clip01(Bv.w / 255.0f), clip01(C.z / 255.0f))));
        m2 = fmaxf(m2, fmaxf(fmaxf(clip01(A.z / 255.0f), clip01(Bv.y / 255.0f)),
                             fmaxf(clip01(C.x / 255.0f), clip01(C.w / 255.0f))));
    }
    atomicMax(&chmaxi[0], __float_as_int(m0));
    atomicMax(&chmaxi[1], __float_as_int(m1));
    atomicMax(&chmaxi[2], __float_as_int(m2));
    __syncthreads();
    const float cm0 = __int_as_float(chmaxi[0]);
    const float cm1 = __int_as_float(chmaxi[1]);
    const float cm2 = __int_as_float(chmaxi[2]);

    const unsigned int kk0 = kp.k[b][pass * 2 + 0];
    const unsigned int kk1 = kp.k[b][pass * 2 + 1];

    // ---- scores + local histogram for this block's pixel half ----
    const int G = NPIX / 4;                   // 2304 groups
    const int gbeg = z * (G / ZSPL);
    const int gend = gbeg + G / ZSPL;
    float* sc_out = &g_score[b][pass][0];

    for (int g = gbeg + t; g < gend; g += 1024) {
        float4 A = im4[g * 3 + 0];
        float4 Bv = im4[g * 3 + 1];
        float4 C = im4[g * 3 + 2];
        float px0[4] = {A.x, A.w, Bv.z, C.y};
        float px1[4] = {A.y, Bv.x, Bv.w, C.z};
        float px2[4] = {A.z, Bv.y, C.x, C.w};
        float sc4[4];
#pragma unroll
        for (int u = 0; u < 4; ++u) {
            int p = 4 * g + u;
            unsigned int bits = tf_bits32(kk0, kk1, (unsigned int)p);
            float v0 = clip01(px0[u] / 255.0f);
            float v1 = clip01(px1[u] / 255.0f);
            float v2 = clip01(px2[u] / 255.0f);
            float n0 = v0 / cm0, n1 = v1 / cm1, n2 = v2 / cm2;
            bool fg = (n0 > 0.f && n0 < 0.6f) ||
                      (n1 > 0.f && n1 < 0.6f) ||
                      (n2 > 0.f && n2 < 0.6f);
            bool valid = pass ? (!fg) : fg;
            float sc = valid ? bits_to_unit_float(bits) : -1.0f;
            sc4[u] = sc;
            if (valid) {
                int bin = min((int)(sc * 256.0f), 255);
                atomicAdd(&hist[bin], 1);
            }
        }
        *(float4*)&sc_out[4 * g] = make_float4(sc4[0], sc4[1], sc4[2], sc4[3]);
    }
    __syncthreads();

    if (t < 256) g_hist[b][pass][z][t] = hist[t];   // full overwrite, no zeroing
}

// ---------------------------------------------------------------------------
// Kernel 1: selection.  grid (NIMG, 2), 1024 thr.  Identical math to before.
// ---------------------------------------------------------------------------
__global__ __launch_bounds__(1024) void k1_select(Keys kp)
{
    const int b = blockIdx.x;
    const int pass = blockIdx.y;
    const int t = threadIdx.x;
    const int lane = t & 31;
    const int warp = t >> 5;

    __shared__ float score[NPIX];             // 36 KB
    __shared__ int   scan[257];
    __shared__ int   cidx[CAP];
    __shared__ int   s_B, s_cnt;
    __shared__ float redv[32];
    __shared__ int   redi[32];

    // copy score slice to smem (float4)
    {
        const float4* src = (const float4*)&g_score[b][pass][0];
        float4* dst = (float4*)score;
        for (int i = t; i < NPIX / 4; i += 1024) dst[i] = src[i];
    }
    if (t < 256) {
        int s = 0;
#pragma unroll
        for (int zz = 0; zz < ZSPL; ++zz) s += g_hist[b][pass][zz][t];
        scan[t] = s;
    }
    if (t == 0) { s_B = -1; s_cnt = 0; }
    __syncthreads();

    // parallel suffix scan over hist (Hillis-Steele, 8 steps)
#pragma unroll
    for (int off = 1; off < 256; off <<= 1) {
        int v = 0;
        if (t < 256 && t + off < 256) v = scan[t + off];
        __syncthreads();
        if (t < 256) scan[t] += v;
        __syncthreads();
    }
    if (t < 256 && scan[t] >= NPC && (t == 255 || scan[t + 1] < NPC)) s_B = t;
    __syncthreads();
    const int B = s_B;

    bool fast_ok = false;
    if (B >= 0) {
        for (int p = t; p < NPIX; p += 1024) {
            float v = score[p];
            if (v >= 0.0f) {
                int bin = min((int)(v * 256.0f), 255);
                if (bin >= B) {
                    int pos = atomicAdd(&s_cnt, 1);
                    if (pos < CAP) cidx[pos] = p;
                }
            }
        }
        __syncthreads();
        const int cnt = s_cnt;
        if (cnt <= CAP) {
            fast_ok = true;
            if (t < cnt) {
                int myi = cidx[t];
                float myv = score[myi];
                int rank = 0;
                for (int j = 0; j < cnt; ++j) {
                    int oj = cidx[j];
                    float ov = score[oj];
                    rank += (ov > myv) || (ov == myv && oj < myi);
                }
                if (rank < NPC) g_sel[b][pass][rank] = myi;
            }
        }
        __syncthreads();
    }

    if (!fast_ok) {
        // fallback: 50 serialized argmax passes (deterministic safety net)
        for (int s = 0; s < NPC; ++s) {
            float bv = -3.0f; int bi = NPIX;
            for (int p = t; p < NPIX; p += 1024) {
                float v = score[p];
                if (v > bv) { bv = v; bi = p; }
            }
#pragma unroll
            for (int off = 16; off > 0; off >>= 1) {
                float ov = __shfl_down_sync(0xffffffffu, bv, off);
                int   oi = __shfl_down_sync(0xffffffffu, bi, off);
                if (ov > bv || (ov == bv && oi < bi)) { bv = ov; bi = oi; }
            }
            if (lane == 0) { redv[warp] = bv; redi[warp] = bi; }
            __syncthreads();
            if (warp == 0) {
                bv = redv[lane]; bi = redi[lane];
#pragma unroll
                for (int off = 16; off > 0; off >>= 1) {
                    float ov = __shfl_down_sync(0xffffffffu, bv, off);
                    int   oi = __shfl_down_sync(0xffffffffu, bi, off);
                    if (ov > bv || (ov == bv && oi < bi)) { bv = ov; bi = oi; }
                }
                if (lane == 0) { g_sel[b][pass][s] = bi; score[bi] = -2.0f; }
            }
            __syncthreads();
        }
    }
}

// ---------------------------------------------------------------------------
// Kernel 1b: train-set build + standardize + negated pair-packed write.
// ---------------------------------------------------------------------------
__global__ __launch_bounds__(256) void k1b_build(const float* __restrict__ img)
{
    const int b = blockIdx.x;
    const int t = threadIdx.x;
    const float* im = img + (size_t)b * NPIX * 3;

    __shared__ float trf[NTRAIN][5];
    __shared__ float smean[5], sstd[5];

    if (t < NTRAIN) {
        int idx = g_sel[b][t / NPC][t % NPC];
        int ii = idx / HW, jj = idx % HW;
        trf[t][0] = clip01(im[idx * 3 + 0] / 255.0f) / 255.0f;
        trf[t][1] = clip01(im[idx * 3 + 1] / 255.0f) / 255.0f;
        trf[t][2] = clip01(im[idx * 3 + 2] / 255.0f) / 255.0f;
        trf[t][3] = (float)ii / 96.0f * 100.0f;
        trf[t][4] = (float)jj / 96.0f * 100.0f;
    }
    __syncthreads();

    if (t < 5) {
        float s = 0.f;
        for (int j = 0; j < NTRAIN; ++j) s += trf[j][t];
        float mean = s / (float)NTRAIN;
        float s2 = 0.f;
        for (int j = 0; j < NTRAIN; ++j) {
            float d = trf[j][t] - mean;
            s2 += d * d;
        }
        float sd = sqrtf(s2 / (float)NTRAIN);
        smean[t] = mean; sstd[t] = sd;
        g_mean[b][t] = mean; g_std[b][t] = sd;
    }
    __syncthreads();

    // negated standardized pairs: flat i -> cls, d, q ; j0=2q, j1=2q+1
    for (int i = t; i < 2 * 5 * NPAIR; i += 256) {
        int cls = i / (5 * NPAIR);
        int r = i % (5 * NPAIR);
        int d = r / NPAIR, q = r % NPAIR;
        int j0 = 2 * q, j1 = 2 * q + 1;
        float a = (j0 < NPC) ? -((trf[cls * NPC + j0][d] - smean[d]) / sstd[d]) : -PADV;
        float c = (j1 < NPC) ? -((trf[cls * NPC + j1][d] - smean[d]) / sstd[d]) : -PADV;
        unsigned int ua = __float_as_uint(a), uc = __float_as_uint(c);
        g_tr2[b][cls][d][q] = ((unsigned long long)uc << 32) | (unsigned long long)ua;
    }
}

// ---------------------------------------------------------------------------
// dsq for one packed pair vs pixel features; exact scalar order per lane.
// ---------------------------------------------------------------------------
__device__ __forceinline__ unsigned long long pair_dsq(
    unsigned long long t0, unsigned long long t1, unsigned long long t2,
    unsigned long long t3, unsigned long long t4,
    unsigned long long F0, unsigned long long F1, unsigned long long F2,
    unsigned long long F3, unsigned long long F4)
{
    unsigned long long d0 = add2(F0, t0);
    unsigned long long d1 = add2(F1, t1);
    unsigned long long d2 = add2(F2, t2);
    unsigned long long d3 = add2(F3, t3);
    unsigned long long d4 = add2(F4, t4);
    unsigned long long acc = mul2(d0, d0);
    acc = fma2(d1, d1, acc);
    acc = fma2(d2, d2, acc);
    acc = fma2(d3, d3, acc);
    acc = fma2(d4, d4, acc);
    return acc;
}

// ---------------------------------------------------------------------------
// Kernel 2: KNN classify + mask.  1 px/thread.
// Vote: seg <=> (2nd-min fg dsq) <= (4th-min bg dsq) <=> #{bg < a1} <= 3.
// (strict < encodes fg-wins-ties; identical semantics to the merged count.)
// ---------------------------------------------------------------------------
__global__ __launch_bounds__(256) void k2_knn(const float* __restrict__ img,
                                              float* __restrict__ out)
{
    const int b = blockIdx.y;
    const int t = threadIdx.x;
    const int p = blockIdx.x * 256 + t;

    __shared__ __align__(16) unsigned long long sneg[2 * 5 * NPAIR];   // 260 u64
    __shared__ float sm[5], ss[5];

    {
        const unsigned long long* src = &g_tr2[b][0][0][0];
        for (int i = t; i < 2 * 5 * NPAIR; i += 256) sneg[i] = src[i];
    }
    if (t < 5)           sm[t] = g_mean[b][t];
    else if (t < 10)     ss[t - 5] = g_std[b][t - 5];
    __syncthreads();

    const float* im = img + (size_t)b * NPIX * 3;

    float v0 = clip01(im[p * 3 + 0] / 255.0f);
    float v1 = clip01(im[p * 3 + 1] / 255.0f);
    float v2 = clip01(im[p * 3 + 2] / 255.0f);

    float f0 = (v0 / 255.0f - sm[0]) / ss[0];
    float f1 = (v1 / 255.0f - sm[1]) / ss[1];
    float f2v = (v2 / 255.0f - sm[2]) / ss[2];
    float f3 = ((float)(p / HW) / 96.0f * 100.0f - sm[3]) / ss[3];
    float f4 = ((float)(p % HW) / 96.0f * 100.0f - sm[4]) / ss[4];

    unsigned long long F0 = pk2(f0, f0), F1 = pk2(f1, f1), F2 = pk2(f2v, f2v),
                       F3 = pk2(f3, f3), F4 = pk2(f4, f4);

    // ---- fg: min2 (m0 <= m1), branch-prefiltered insert ----
    float m0 = 1e38f, m1 = 1e38f;
    {
        const ulonglong2* tr2 = (const ulonglong2*)&sneg[0];
#pragma unroll
        for (int j = 0; j < NPAIR / 2; ++j) {
            ulonglong2 T0 = tr2[13 * 0 + j];
            ulonglong2 T1 = tr2[13 * 1 + j];
            ulonglong2 T2 = tr2[13 * 2 + j];
            ulonglong2 T3 = tr2[13 * 3 + j];
            ulonglong2 T4 = tr2[13 * 4 + j];
            unsigned long long accA = pair_dsq(T0.x, T1.x, T2.x, T3.x, T4.x,
                                               F0, F1, F2, F3, F4);
            unsigned long long accB = pair_dsq(T0.y, T1.y, T2.y, T3.y, T4.y,
                                               F0, F1, F2, F3, F4);
            float lA, hA, lB, hB;
            upk2(lA, hA, accA);
            upk2(lB, hB, accB);
            float mn = fminf(fminf(lA, hA), fminf(lB, hB));
            if (mn < m1) {
                // exact multiset min2 via fmin/fmax (order-independent)
                float nm0 = fminf(m0, lA); m1 = fminf(m1, fmaxf(m0, lA)); m0 = nm0;
                nm0 = fminf(m0, hA); m1 = fminf(m1, fmaxf(m0, hA)); m0 = nm0;
                nm0 = fminf(m0, lB); m1 = fminf(m1, fmaxf(m0, lB)); m0 = nm0;
                nm0 = fminf(m0, hB); m1 = fminf(m1, fmaxf(m0, hB)); m0 = nm0;
            }
        }
    }
    const float a1 = m1;

    // ---- bg: branchless count of dsq strictly below a1 ----
    int cnt = 0;
    {
        const ulonglong2* tr2 = (const ulonglong2*)&sneg[5 * NPAIR];
#pragma unroll
        for (int j = 0; j < NPAIR / 2; ++j) {
            ulonglong2 T0 = tr2[13 * 0 + j];
            ulonglong2 T1 = tr2[13 * 1 + j];
            ulonglong2 T2 = tr2[13 * 2 + j];
            ulonglong2 T3 = tr2[13 * 3 + j];
            ulonglong2 T4 = tr2[13 * 4 + j];
            unsigned long long accA = pair_dsq(T0.x, T1.x, T2.x, T3.x, T4.x,
                                               F0, F1, F2, F3, F4);
            unsigned long long accB = pair_dsq(T0.y, T1.y, T2.y, T3.y, T4.y,
                                               F0, F1, F2, F3, F4);
            float lA, hA, lB, hB;
            upk2(lA, hA, accA);
            upk2(lB, hB, accB);
            cnt += (lA < a1) + (hA < a1) + (lB < a1) + (hB < a1);
        }
    }
    bool seg = (cnt <= 3);   // #{bg < a1} <= 3  <=>  >=2 fg in merged top-5

    float* o = out + (size_t)b * NPIX * 3 + (size_t)p * 3;
    o[0] = seg ? v0 : 0.0f;
    o[1] = seg ? v1 : 0.0f;
    o[2] = seg ? v2 : 0.0f;
}

// ---------------------------------------------------------------------------
// host: derive JAX keys — partitionable threefry (default since JAX 0.4.36)
// ---------------------------------------------------------------------------
static void compute_keys(Keys& kp)
{
    for (int b = 0; b < NIMG; ++b) {
        unsigned int ik0, ik1;
        threefry2x32(0u, 42u, 0u, (unsigned int)b, ik0, ik1);   // split(key(42),32)[b]
        unsigned int f0, f1, g0, g1;
        threefry2x32(ik0, ik1, 0u, 0u, f0, f1);                 // split(imgkey)[0] = k_fg
        threefry2x32(ik0, ik1, 0u, 1u, g0, g1);                 // split(imgkey)[1] = k_bg
        kp.k[b][0] = f0; kp.k[b][1] = f1;
        kp.k[b][2] = g0; kp.k[b][3] = g1;
    }
}

extern "C" void kernel_launch(void* const* d_in, const int* in_sizes, int n_in,
                              void* d_out, int out_size)
{
    const float* img = (const float*)d_in[0];
    float* out = (float*)d_out;
    (void)in_sizes; (void)n_in; (void)out_size;

    Keys kp;
    compute_keys(kp);

    dim3 g0(NIMG, 2, ZSPL);
    k0_score<<<g0, 1024>>>(img, kp);
    dim3 g1(NIMG, 2);
    k1_select<<<g1, 1024>>>(kp);
    k1b_build<<<NIMG, 256>>>(img);
    dim3 g2(NPIX / 256, NIMG);
    k2_knn<<<g2, 256>>>(img, out);
}

// round 13
// speedup vs baseline: 1.5013x; 1.5013x over previous
#include <cuda_runtime.h>
#include <stdint.h>

#define HW    96
#define NPIX  9216          // 96*96
#define NIMG  32
#define NTRAIN 100
#define NPC   50
#define NPAD  52            // per-class padded train count (26 pairs)
#define NPAIR 26
#define CAP   1024
#define PADV  1.0e18f

struct Keys { unsigned int k[NIMG][4]; };   // per image: kfg0,kfg1,kbg0,kbg1

// ---------------------------------------------------------------------------
// packed f32x2 helpers (sm_103a: two fp32 lanes per FMA-pipe op, rn rounding)
// ---------------------------------------------------------------------------
__device__ __forceinline__ unsigned long long pk2(float lo, float hi)
{
    unsigned long long o;
    asm("mov.b64 %0, {%1, %2};" : "=l"(o) : "f"(lo), "f"(hi));
    return o;
}
__device__ __forceinline__ void upk2(float &lo, float &hi, unsigned long long v)
{
    asm("mov.b64 {%0, %1}, %2;" : "=f"(lo), "=f"(hi) : "l"(v));
}
__device__ __forceinline__ unsigned long long add2(unsigned long long a, unsigned long long b)
{
    unsigned long long o;
    asm("add.rn.f32x2 %0, %1, %2;" : "=l"(o) : "l"(a), "l"(b));
    return o;
}
__device__ __forceinline__ unsigned long long mul2(unsigned long long a, unsigned long long b)
{
    unsigned long long o;
    asm("mul.rn.f32x2 %0, %1, %2;" : "=l"(o) : "l"(a), "l"(b));
    return o;
}
__device__ __forceinline__ unsigned long long fma2(unsigned long long a, unsigned long long b,
                                                   unsigned long long c)
{
    unsigned long long o;
    asm("fma.rn.f32x2 %0, %1, %2, %3;" : "=l"(o) : "l"(a), "l"(b), "l"(c));
    return o;
}

// ---------------------------------------------------------------------------
// threefry2x32 (JAX-exact)
// ---------------------------------------------------------------------------
__host__ __device__ __forceinline__ void threefry2x32(
    unsigned int k0, unsigned int k1,
    unsigned int x0, unsigned int x1,
    unsigned int &o0, unsigned int &o1)
{
    unsigned int ks[3];
    ks[0] = k0; ks[1] = k1; ks[2] = k0 ^ k1 ^ 0x1BD11BDAu;
    x0 += ks[0]; x1 += ks[1];
    const int rot[8] = {13, 15, 26, 6, 17, 29, 16, 24};
#pragma unroll
    for (int i = 0; i < 5; ++i) {
#pragma unroll
        for (int j = 0; j < 4; ++j) {
            int r = rot[(i & 1) * 4 + j];
            x0 += x1;
            x1 = (x1 << r) | (x1 >> (32 - r));
            x1 ^= x0;
        }
        x0 += ks[(i + 1) % 3];
        x1 += ks[(i + 2) % 3] + (unsigned int)(i + 1);
    }
    o0 = x0; o1 = x1;
}

// partitionable-mode 32-bit random word for flat index i (iota64: hi=0, lo=i)
__device__ __forceinline__ unsigned int tf_bits32(unsigned int k0, unsigned int k1,
                                                  unsigned int i)
{
    unsigned int r0, r1;
    threefry2x32(k0, k1, 0u, i, r0, r1);
    return r0 ^ r1;
}

__device__ __forceinline__ float bits_to_unit_float(unsigned int bits)
{
    unsigned int fb = (bits >> 9) | 0x3f800000u;
    return __uint_as_float(fb) - 1.0f;
}

__device__ __forceinline__ float clip01(float x)
{
    return fminf(fmaxf(x, 0.0f), 1.0f);
}

// ---------------------------------------------------------------------------
// scratch (no cudaMalloc allowed)
// ---------------------------------------------------------------------------
__device__ int                g_sel[NIMG][2][NPC];
__device__ unsigned long long g_tr2[NIMG][2][5][NPAIR];  // NEGATED std. train pairs
__device__ float              g_mean[NIMG][5];
__device__ float              g_std[NIMG][5];

// ---------------------------------------------------------------------------
// Kernel 1: per-(image,class) sampling.  grid (NIMG, 2), 1024 thr.
// (R11 structure — combined hash + histogram selection; split reverted.)
// ---------------------------------------------------------------------------
__global__ __launch_bounds__(1024) void k1_sample(const float* __restrict__ img, Keys kp)
{
    const int b = blockIdx.x;
    const int pass = blockIdx.y;              // 0 = fg, 1 = bg
    const int t = threadIdx.x;
    const int lane = t & 31;
    const int warp = t >> 5;
    const float* im = img + (size_t)b * NPIX * 3;
    const float4* im4 = (const float4*)im;    // 4 px = 3 float4

    __shared__ float score[NPIX];             // 36 KB
    __shared__ int   hist[256];
    __shared__ int   scan[257];
    __shared__ int   cidx[CAP];
    __shared__ int   s_B, s_cnt;
    __shared__ float redv[32];
    __shared__ int   redi[32];
    __shared__ int   chmaxi[3];

    if (t < 3) chmaxi[t] = 0;
    if (t < 256) hist[t] = 0;
    if (t == 0) { s_B = -1; s_cnt = 0; }
    __syncthreads();

    // ---- channel max over 4-px groups ----
    float m0 = 0.f, m1 = 0.f, m2 = 0.f;
    for (int g = t; g < NPIX / 4; g += 1024) {
        float4 A = im4[g * 3 + 0];
        float4 Bv = im4[g * 3 + 1];
        float4 C = im4[g * 3 + 2];
        m0 = fmaxf(m0, fmaxf(fmaxf(clip01(A.x / 255.0f), clip01(A.w / 255.0f)),
                             fmaxf(clip01(Bv.z / 255.0f), clip01(C.y / 255.0f))));
        m1 = fmaxf(m1, fmaxf(fmaxf(clip01(A.y / 255.0f), clip01(Bv.x / 255.0f)),
                             fmaxf(clip01(Bv.w / 255.0f), clip01(C.z / 255.0f))));
        m2 = fmaxf(m2, fmaxf(fmaxf(clip01(A.z / 255.0f), clip01(Bv.y / 255.0f)),
                             fmaxf(clip01(C.x / 255.0f), clip01(C.w / 255.0f))));
    }
    atomicMax(&chmaxi[0], __float_as_int(m0));
    atomicMax(&chmaxi[1], __float_as_int(m1));
    atomicMax(&chmaxi[2], __float_as_int(m2));
    __syncthreads();
    const float cm0 = __int_as_float(chmaxi[0]);
    const float cm1 = __int_as_float(chmaxi[1]);
    const float cm2 = __int_as_float(chmaxi[2]);

    const unsigned int kk0 = kp.k[b][pass * 2 + 0];
    const unsigned int kk1 = kp.k[b][pass * 2 + 1];

    // ---- scores + histogram, 4 px per iteration ----
    for (int g = t; g < NPIX / 4; g += 1024) {
        float4 A = im4[g * 3 + 0];
        float4 Bv = im4[g * 3 + 1];
        float4 C = im4[g * 3 + 2];
        float px0[4] = {A.x, A.w, Bv.z, C.y};
        float px1[4] = {A.y, Bv.x, Bv.w, C.z};
        float px2[4] = {A.z, Bv.y, C.x, C.w};
        float sc4[4];
#pragma unroll
        for (int u = 0; u < 4; ++u) {
            int p = 4 * g + u;
            unsigned int bits = tf_bits32(kk0, kk1, (unsigned int)p);
            float v0 = clip01(px0[u] / 255.0f);
            float v1 = clip01(px1[u] / 255.0f);
            float v2 = clip01(px2[u] / 255.0f);
            float n0 = v0 / cm0, n1 = v1 / cm1, n2 = v2 / cm2;
            bool fg = (n0 > 0.f && n0 < 0.6f) ||
                      (n1 > 0.f && n1 < 0.6f) ||
                      (n2 > 0.f && n2 < 0.6f);
            bool valid = pass ? (!fg) : fg;
            float sc = valid ? bits_to_unit_float(bits) : -1.0f;
            sc4[u] = sc;
            if (valid) {
                int bin = min((int)(sc * 256.0f), 255);
                atomicAdd(&hist[bin], 1);
            }
        }
        *(float4*)&score[4 * g] = make_float4(sc4[0], sc4[1], sc4[2], sc4[3]);
    }
    __syncthreads();

    // parallel suffix scan over hist (Hillis-Steele, 8 steps)
    if (t < 256) scan[t] = hist[t];
    __syncthreads();
#pragma unroll
    for (int off = 1; off < 256; off <<= 1) {
        int v = 0;
        if (t < 256 && t + off < 256) v = scan[t + off];
        __syncthreads();
        if (t < 256) scan[t] += v;
        __syncthreads();
    }
    if (t < 256 && scan[t] >= NPC && (t == 255 || scan[t + 1] < NPC)) s_B = t;
    __syncthreads();
    const int B = s_B;

    bool fast_ok = false;
    if (B >= 0) {
        for (int p = t; p < NPIX; p += 1024) {
            float v = score[p];
            if (v >= 0.0f) {
                int bin = min((int)(v * 256.0f), 255);
                if (bin >= B) {
                    int pos = atomicAdd(&s_cnt, 1);
                    if (pos < CAP) cidx[pos] = p;
                }
            }
        }
        __syncthreads();
        const int cnt = s_cnt;
        if (cnt <= CAP) {
            fast_ok = true;
            if (t < cnt) {
                int myi = cidx[t];
                float myv = score[myi];
                int rank = 0;
                for (int j = 0; j < cnt; ++j) {
                    int oj = cidx[j];
                    float ov = score[oj];
                    rank += (ov > myv) || (ov == myv && oj < myi);
                }
                if (rank < NPC) g_sel[b][pass][rank] = myi;
            }
        }
        __syncthreads();
    }

    if (!fast_ok) {
        // fallback: 50 serialized argmax passes (deterministic safety net)
        for (int s = 0; s < NPC; ++s) {
            float bv = -3.0f; int bi = NPIX;
            for (int p = t; p < NPIX; p += 1024) {
                float v = score[p];
                if (v > bv) { bv = v; bi = p; }
            }
#pragma unroll
            for (int off = 16; off > 0; off >>= 1) {
                float ov = __shfl_down_sync(0xffffffffu, bv, off);
                int   oi = __shfl_down_sync(0xffffffffu, bi, off);
                if (ov > bv || (ov == bv && oi < bi)) { bv = ov; bi = oi; }
            }
            if (lane == 0) { redv[warp] = bv; redi[warp] = bi; }
            __syncthreads();
            if (warp == 0) {
                bv = redv[lane]; bi = redi[lane];
#pragma unroll
                for (int off = 16; off > 0; off >>= 1) {
                    float ov = __shfl_down_sync(0xffffffffu, bv, off);
                    int   oi = __shfl_down_sync(0xffffffffu, bi, off);
                    if (ov > bv || (ov == bv && oi < bi)) { bv = ov; bi = oi; }
                }
                if (lane == 0) { g_sel[b][pass][s] = bi; score[bi] = -2.0f; }
            }
            __syncthreads();
        }
    }
}

// ---------------------------------------------------------------------------
// Kernel 1b: train-set build + standardize + negated pair-packed write.
// ---------------------------------------------------------------------------
__global__ __launch_bounds__(256) void k1b_build(const float* __restrict__ img)
{
    const int b = blockIdx.x;
    const int t = threadIdx.x;
    const float* im = img + (size_t)b * NPIX * 3;

    __shared__ float trf[NTRAIN][5];
    __shared__ float smean[5], sstd[5];

    if (t < NTRAIN) {
        int idx = g_sel[b][t / NPC][t % NPC];
        int ii = idx / HW, jj = idx % HW;
        trf[t][0] = clip01(im[idx * 3 + 0] / 255.0f) / 255.0f;
        trf[t][1] = clip01(im[idx * 3 + 1] / 255.0f) / 255.0f;
        trf[t][2] = clip01(im[idx * 3 + 2] / 255.0f) / 255.0f;
        trf[t][3] = (float)ii / 96.0f * 100.0f;
        trf[t][4] = (float)jj / 96.0f * 100.0f;
    }
    __syncthreads();

    if (t < 5) {
        float s = 0.f;
        for (int j = 0; j < NTRAIN; ++j) s += trf[j][t];
        float mean = s / (float)NTRAIN;
        float s2 = 0.f;
        for (int j = 0; j < NTRAIN; ++j) {
            float d = trf[j][t] - mean;
            s2 += d * d;
        }
        float sd = sqrtf(s2 / (float)NTRAIN);
        smean[t] = mean; sstd[t] = sd;
        g_mean[b][t] = mean; g_std[b][t] = sd;
    }
    __syncthreads();

    // negated standardized pairs: flat i -> cls, d, q ; j0=2q, j1=2q+1
    for (int i = t; i < 2 * 5 * NPAIR; i += 256) {
        int cls = i / (5 * NPAIR);
        int r = i % (5 * NPAIR);
        int d = r / NPAIR, q = r % NPAIR;
        int j0 = 2 * q, j1 = 2 * q + 1;
        float a = (j0 < NPC) ? -((trf[cls * NPC + j0][d] - smean[d]) / sstd[d]) : -PADV;
        float c = (j1 < NPC) ? -((trf[cls * NPC + j1][d] - smean[d]) / sstd[d]) : -PADV;
        unsigned int ua = __float_as_uint(a), uc = __float_as_uint(c);
        g_tr2[b][cls][d][q] = ((unsigned long long)uc << 32) | (unsigned long long)ua;
    }
}

// ---------------------------------------------------------------------------
// dsq for one packed pair vs pixel features; exact scalar order per lane.
// ---------------------------------------------------------------------------
__device__ __forceinline__ unsigned long long pair_dsq(
    unsigned long long t0, unsigned long long t1, unsigned long long t2,
    unsigned long long t3, unsigned long long t4,
    unsigned long long F0, unsigned long long F1, unsigned long long F2,
    unsigned long long F3, unsigned long long F4)
{
    unsigned long long d0 = add2(F0, t0);
    unsigned long long d1 = add2(F1, t1);
    unsigned long long d2 = add2(F2, t2);
    unsigned long long d3 = add2(F3, t3);
    unsigned long long d4 = add2(F4, t4);
    unsigned long long acc = mul2(d0, d0);
    acc = fma2(d1, d1, acc);
    acc = fma2(d2, d2, acc);
    acc = fma2(d3, d3, acc);
    acc = fma2(d4, d4, acc);
    return acc;
}

// exact multiset min2 update with 4 candidates (m0 <= m1 maintained)
__device__ __forceinline__ void min2_upd(float v, float &m0, float &m1)
{
    float nm0 = fminf(m0, v);
    m1 = fminf(m1, fmaxf(m0, v));
    m0 = nm0;
}

// ---------------------------------------------------------------------------
// Kernel 2: KNN classify + mask.  2 px/thread (train LDS amortized), f32x2.
// Vote: seg <=> #{bg dsq < a1} <= 3  (a1 = 2nd-min fg; strict < = fg ties win)
// ---------------------------------------------------------------------------
#define PXB 512
__global__ __launch_bounds__(256) void k2_knn(const float* __restrict__ img,
                                              float* __restrict__ out)
{
    const int b = blockIdx.y;
    const int t = threadIdx.x;
    const int p0 = blockIdx.x * PXB + t;
    const int p1 = p0 + 256;

    __shared__ __align__(16) unsigned long long sneg[2 * 5 * NPAIR];   // 260 u64
    __shared__ float sm[5], ss[5];

    {
        const unsigned long long* src = &g_tr2[b][0][0][0];
        for (int i = t; i < 2 * 5 * NPAIR; i += 256) sneg[i] = src[i];
    }
    if (t < 5)           sm[t] = g_mean[b][t];
    else if (t < 10)     ss[t - 5] = g_std[b][t - 5];
    __syncthreads();

    const float* im = img + (size_t)b * NPIX * 3;

    float v0[2], v1[2], v2[2];
    unsigned long long F0[2], F1[2], F2[2], F3[2], F4[2];
#pragma unroll
    for (int x = 0; x < 2; ++x) {
        int p = x ? p1 : p0;
        v0[x] = clip01(im[p * 3 + 0] / 255.0f);
        v1[x] = clip01(im[p * 3 + 1] / 255.0f);
        v2[x] = clip01(im[p * 3 + 2] / 255.0f);
        float f0 = (v0[x] / 255.0f - sm[0]) / ss[0];
        float f1 = (v1[x] / 255.0f - sm[1]) / ss[1];
        float f2 = (v2[x] / 255.0f - sm[2]) / ss[2];
        float f3 = ((float)(p / HW) / 96.0f * 100.0f - sm[3]) / ss[3];
        float f4 = ((float)(p % HW) / 96.0f * 100.0f - sm[4]) / ss[4];
        F0[x] = pk2(f0, f0); F1[x] = pk2(f1, f1); F2[x] = pk2(f2, f2);
        F3[x] = pk2(f3, f3); F4[x] = pk2(f4, f4);
    }

    // ---- fg: min2 per pixel ----
    float a_m0[2] = {1e38f, 1e38f}, a_m1[2] = {1e38f, 1e38f};
    {
        const ulonglong2* tr2 = (const ulonglong2*)&sneg[0];
#pragma unroll
        for (int j = 0; j < NPAIR / 2; ++j) {
            ulonglong2 T0 = tr2[13 * 0 + j];
            ulonglong2 T1 = tr2[13 * 1 + j];
            ulonglong2 T2 = tr2[13 * 2 + j];
            ulonglong2 T3 = tr2[13 * 3 + j];
            ulonglong2 T4 = tr2[13 * 4 + j];
#pragma unroll
            for (int x = 0; x < 2; ++x) {
                unsigned long long accA = pair_dsq(T0.x, T1.x, T2.x, T3.x, T4.x,
                                                   F0[x], F1[x], F2[x], F3[x], F4[x]);
                unsigned long long accB = pair_dsq(T0.y, T1.y, T2.y, T3.y, T4.y,
                                                   F0[x], F1[x], F2[x], F3[x], F4[x]);
                float lA, hA, lB, hB;
                upk2(lA, hA, accA);
                upk2(lB, hB, accB);
                float mn = fminf(fminf(lA, hA), fminf(lB, hB));
                if (mn < a_m1[x]) {
                    min2_upd(lA, a_m0[x], a_m1[x]);
                    min2_upd(hA, a_m0[x], a_m1[x]);
                    min2_upd(lB, a_m0[x], a_m1[x]);
                    min2_upd(hB, a_m0[x], a_m1[x]);
                }
            }
        }
    }

    // ---- bg: branchless count strictly below a1, per pixel ----
    int cnt[2] = {0, 0};
    {
        const ulonglong2* tr2 = (const ulonglong2*)&sneg[5 * NPAIR];
#pragma unroll
        for (int j = 0; j < NPAIR / 2; ++j) {
            ulonglong2 T0 = tr2[13 * 0 + j];
            ulonglong2 T1 = tr2[13 * 1 + j];
            ulonglong2 T2 = tr2[13 * 2 + j];
            ulonglong2 T3 = tr2[13 * 3 + j];
            ulonglong2 T4 = tr2[13 * 4 + j];
#pragma unroll
            for (int x = 0; x < 2; ++x) {
                unsigned long long accA = pair_dsq(T0.x, T1.x, T2.x, T3.x, T4.x,
                                                   F0[x], F1[x], F2[x], F3[x], F4[x]);
                unsigned long long accB = pair_dsq(T0.y, T1.y, T2.y, T3.y, T4.y,
                                                   F0[x], F1[x], F2[x], F3[x], F4[x]);
                float lA, hA, lB, hB;
                upk2(lA, hA, accA);
                upk2(lB, hB, accB);
                cnt[x] += (lA < a_m1[x]) + (hA < a_m1[x]) + (lB < a_m1[x]) + (hB < a_m1[x]);
            }
        }
    }

#pragma unroll
    for (int x = 0; x < 2; ++x) {
        int p = x ? p1 : p0;
        bool seg = (cnt[x] <= 3);   // >=2 fg in merged top-5
        float* o = out + (size_t)b * NPIX * 3 + (size_t)p * 3;
        o[0] = seg ? v0[x] : 0.0f;
        o[1] = seg ? v1[x] : 0.0f;
        o[2] = seg ? v2[x] : 0.0f;
    }
}

// ---------------------------------------------------------------------------
// host: derive JAX keys — partitionable threefry (default since JAX 0.4.36)
// ---------------------------------------------------------------------------
static void compute_keys(Keys& kp)
{
    for (int b = 0; b < NIMG; ++b) {
        unsigned int ik0, ik1;
        threefry2x32(0u, 42u, 0u, (unsigned int)b, ik0, ik1);   // split(key(42),32)[b]
        unsigned int f0, f1, g0, g1;
        threefry2x32(ik0, ik1, 0u, 0u, f0, f1);                 // split(imgkey)[0] = k_fg
        threefry2x32(ik0, ik1, 0u, 1u, g0, g1);                 // split(imgkey)[1] = k_bg
        kp.k[b][0] = f0; kp.k[b][1] = f1;
        kp.k[b][2] = g0; kp.k[b][3] = g1;
    }
}

extern "C" void kernel_launch(void* const* d_in, const int* in_sizes, int n_in,
                              void* d_out, int out_size)
{
    const float* img = (const float*)d_in[0];
    float* out = (float*)d_out;
    (void)in_sizes; (void)n_in; (void)out_size;

    Keys kp;
    compute_keys(kp);

    dim3 g1(NIMG, 2);
    k1_sample<<<g1, 1024>>>(img, kp);
    k1b_build<<<NIMG, 256>>>(img);
    dim3 g2(NPIX / PXB, NIMG);
    k2_knn<<<g2, 256>>>(img, out);
}